// round 2
// baseline (speedup 1.0000x reference)
#include <cuda_runtime.h>
#include <math.h>

// Problem constants
#define BATCH   4
#define NSEQ    8192
#define CDIM    512
#define HEADS   8
#define HDIM    64
#define MROWS   (BATCH * NSEQ)      // 32768
#define QKVN    (3 * CDIM)          // 1536
#define SCALE   0.125f              // 64^-0.5

// ---- scratch (device globals; no allocation allowed) ----
// g_kb doubles as the attention-output buffer: phi(k) is consumed by
// kv_partial_kernel, which completes before attn_apply_kernel overwrites it.
__device__ float g_qb[MROWS * CDIM];     // phi(q), layout [m, h*64+d]
__device__ float g_kb[MROWS * CDIM];     // phi(k), later: attention output
__device__ float g_vb[MROWS * CDIM];     // v
#define KV_CHUNKS 32
__device__ float g_partial[KV_CHUNKS * BATCH * HEADS * HDIM * HDIM]; // 32*32*4096
__device__ float g_kv[BATCH * HEADS * HDIM * HDIM];                  // 32*4096

// ============================================================
// SGEMM 128x128x8, 8x8 per thread, 256 threads.
// C[m,n] = sum_k A[m,k] * W[n,k]   (A row-major MxK, W row-major NxK)
// ============================================================
#define BM 128
#define BN 128
#define BK 8
#define TM 8
#define TN 8

__device__ __forceinline__ float phi_f(float x) {
    // elu(x)+1 : x>0 -> x+1 ; else exp(x)
    return (x > 0.0f) ? (x + 1.0f) : expf(x);
}

// Fused qkv GEMM + phi + scatter to q/k/v buffers
__global__ __launch_bounds__(256) void gemm_qkv_kernel(
    const float* __restrict__ A,   // x: [MROWS, 512]
    const float* __restrict__ W)   // w_qkv: [1536, 512]
{
    const int K = CDIM;
    const int m0 = blockIdx.y * BM;
    const int n0 = blockIdx.x * BN;

    __shared__ float As[BK][BM];
    __shared__ float Bs[BK][BN];

    const int tid = threadIdx.x;
    const int tx = tid & 15;
    const int ty = tid >> 4;

    const int lrow = tid >> 1;          // 0..127
    const int lseg = (tid & 1) * 4;     // 0 or 4

    const float* Aptr = A + (m0 + lrow) * K + lseg;
    const float* Wptr = W + (n0 + lrow) * K + lseg;

    float acc[TM][TN];
    #pragma unroll
    for (int i = 0; i < TM; i++)
        #pragma unroll
        for (int j = 0; j < TN; j++) acc[i][j] = 0.0f;

    for (int k0 = 0; k0 < K; k0 += BK) {
        float4 av = *(const float4*)(Aptr + k0);
        float4 bv = *(const float4*)(Wptr + k0);
        As[lseg + 0][lrow] = av.x;
        As[lseg + 1][lrow] = av.y;
        As[lseg + 2][lrow] = av.z;
        As[lseg + 3][lrow] = av.w;
        Bs[lseg + 0][lrow] = bv.x;
        Bs[lseg + 1][lrow] = bv.y;
        Bs[lseg + 2][lrow] = bv.z;
        Bs[lseg + 3][lrow] = bv.w;
        __syncthreads();

        #pragma unroll
        for (int k = 0; k < BK; k++) {
            float af[TM], bf[TN];
            #pragma unroll
            for (int i = 0; i < TM; i++) af[i] = As[k][ty * TM + i];
            #pragma unroll
            for (int j = 0; j < TN; j++) bf[j] = Bs[k][tx * TN + j];
            #pragma unroll
            for (int i = 0; i < TM; i++)
                #pragma unroll
                for (int j = 0; j < TN; j++)
                    acc[i][j] += af[i] * bf[j];
        }
        __syncthreads();
    }

    // epilogue: n0 is a multiple of 128 so the whole block maps to one of q/k/v
    const int s = n0 >> 9;              // 0=q, 1=k, 2=v
    float* out = (s == 0) ? g_qb : (s == 1) ? g_kb : g_vb;
    const int c0 = (n0 & 511);
    #pragma unroll
    for (int i = 0; i < TM; i++) {
        const int m = m0 + ty * TM + i;
        #pragma unroll
        for (int j = 0; j < TN; j++) {
            const int c = c0 + tx * TN + j;
            float v = acc[i][j];
            if (s < 2) v = phi_f(v);
            out[m * CDIM + c] = v;
        }
    }
}

// proj GEMM with bias: y = attn @ Wp^T + b  (attn lives in g_kb)
__global__ __launch_bounds__(256) void gemm_proj_kernel(
    const float* __restrict__ W,    // w_proj: [512, 512]
    const float* __restrict__ bias, // [512]
    float* __restrict__ Y)          // [MROWS, 512]
{
    const float* A = g_kb;
    const int K = CDIM;
    const int m0 = blockIdx.y * BM;
    const int n0 = blockIdx.x * BN;

    __shared__ float As[BK][BM];
    __shared__ float Bs[BK][BN];

    const int tid = threadIdx.x;
    const int tx = tid & 15;
    const int ty = tid >> 4;

    const int lrow = tid >> 1;
    const int lseg = (tid & 1) * 4;

    const float* Aptr = A + (m0 + lrow) * K + lseg;
    const float* Wptr = W + (n0 + lrow) * K + lseg;

    float acc[TM][TN];
    #pragma unroll
    for (int i = 0; i < TM; i++)
        #pragma unroll
        for (int j = 0; j < TN; j++) acc[i][j] = 0.0f;

    for (int k0 = 0; k0 < K; k0 += BK) {
        float4 av = *(const float4*)(Aptr + k0);
        float4 bv = *(const float4*)(Wptr + k0);
        As[lseg + 0][lrow] = av.x;
        As[lseg + 1][lrow] = av.y;
        As[lseg + 2][lrow] = av.z;
        As[lseg + 3][lrow] = av.w;
        Bs[lseg + 0][lrow] = bv.x;
        Bs[lseg + 1][lrow] = bv.y;
        Bs[lseg + 2][lrow] = bv.z;
        Bs[lseg + 3][lrow] = bv.w;
        __syncthreads();

        #pragma unroll
        for (int k = 0; k < BK; k++) {
            float af[TM], bf[TN];
            #pragma unroll
            for (int i = 0; i < TM; i++) af[i] = As[k][ty * TM + i];
            #pragma unroll
            for (int j = 0; j < TN; j++) bf[j] = Bs[k][tx * TN + j];
            #pragma unroll
            for (int i = 0; i < TM; i++)
                #pragma unroll
                for (int j = 0; j < TN; j++)
                    acc[i][j] += af[i] * bf[j];
        }
        __syncthreads();
    }

    #pragma unroll
    for (int i = 0; i < TM; i++) {
        const int m = m0 + ty * TM + i;
        #pragma unroll
        for (int j = 0; j < TN; j++) {
            const int c = n0 + tx * TN + j;
            Y[m * CDIM + c] = acc[i][j] + bias[c];
        }
    }
}

// ============================================================
// kv partials: per (bh, chunk): acc[d][e] = sum_{n in chunk} phi_k[n,d]*v[n,e]
// ============================================================
__global__ __launch_bounds__(256) void kv_partial_kernel()
{
    const int ch = blockIdx.x;                  // 0..31
    const int bh = blockIdx.y;                  // 0..31
    const int b = bh >> 3, h = bh & 7;
    const int rows = NSEQ / KV_CHUNKS;          // 256
    const int base_m = b * NSEQ + ch * rows;

    const int t = threadIdx.x;
    const int d0 = (t >> 4) * 4;
    const int e0 = (t & 15) * 4;

    __shared__ float ks[4][64];
    __shared__ float vs[4][64];

    float acc[4][4];
    #pragma unroll
    for (int i = 0; i < 4; i++)
        #pragma unroll
        for (int j = 0; j < 4; j++) acc[i][j] = 0.0f;

    const int lr = t >> 6;    // 0..3
    const int lc = t & 63;    // 0..63

    for (int n = 0; n < rows; n += 4) {
        const int m = base_m + n + lr;
        ks[lr][lc] = g_kb[m * CDIM + h * HDIM + lc];
        vs[lr][lc] = g_vb[m * CDIM + h * HDIM + lc];
        __syncthreads();
        #pragma unroll
        for (int r = 0; r < 4; r++) {
            float a0 = ks[r][d0 + 0], a1 = ks[r][d0 + 1], a2 = ks[r][d0 + 2], a3 = ks[r][d0 + 3];
            float b0 = vs[r][e0 + 0], b1 = vs[r][e0 + 1], b2 = vs[r][e0 + 2], b3 = vs[r][e0 + 3];
            acc[0][0] += a0 * b0; acc[0][1] += a0 * b1; acc[0][2] += a0 * b2; acc[0][3] += a0 * b3;
            acc[1][0] += a1 * b0; acc[1][1] += a1 * b1; acc[1][2] += a1 * b2; acc[1][3] += a1 * b3;
            acc[2][0] += a2 * b0; acc[2][1] += a2 * b1; acc[2][2] += a2 * b2; acc[2][3] += a2 * b3;
            acc[3][0] += a3 * b0; acc[3][1] += a3 * b1; acc[3][2] += a3 * b2; acc[3][3] += a3 * b3;
        }
        __syncthreads();
    }

    float* p = g_partial + (ch * (BATCH * HEADS) + bh) * (HDIM * HDIM);
    #pragma unroll
    for (int i = 0; i < 4; i++)
        #pragma unroll
        for (int j = 0; j < 4; j++)
            p[(d0 + i) * HDIM + (e0 + j)] = acc[i][j];
}

// deterministic fixed-order reduce over chunks, apply SCALE
__global__ __launch_bounds__(256) void kv_reduce_kernel()
{
    const int idx = blockIdx.x * 256 + threadIdx.x;   // < 32*4096 = 131072
    const int bh = idx >> 12;
    const int de = idx & 4095;
    float s = 0.0f;
    #pragma unroll
    for (int ch = 0; ch < KV_CHUNKS; ch++)
        s += g_partial[(ch * (BATCH * HEADS) + bh) * (HDIM * HDIM) + de];
    g_kv[idx] = s * SCALE;
}

// ============================================================
// apply: out[n,e] = sum_d phi_q[n,d] * kv[d,e]   per (b,h), 64-row chunks
// writes into g_kb (phi(k) is dead by now)
// ============================================================
__global__ __launch_bounds__(256) void attn_apply_kernel()
{
    const int ch = blockIdx.x;     // 0..127  (chunks of 64 rows)
    const int bh = blockIdx.y;     // 0..31
    const int b = bh >> 3, h = bh & 7;

    __shared__ float kvs[64][65];
    __shared__ float qs[64][65];

    const int t = threadIdx.x;

    #pragma unroll
    for (int i = 0; i < 16; i++) {
        const int idx = i * 256 + t;
        const int r = idx >> 6, d = idx & 63;
        kvs[r][d] = g_kv[bh * (HDIM * HDIM) + idx];
        qs[r][d]  = g_qb[(b * NSEQ + ch * 64 + r) * CDIM + h * HDIM + d];
    }
    __syncthreads();

    const int r0 = (t >> 4) * 4;
    const int e0 = (t & 15) * 4;

    float acc[4][4];
    #pragma unroll
    for (int i = 0; i < 4; i++)
        #pragma unroll
        for (int j = 0; j < 4; j++) acc[i][j] = 0.0f;

    #pragma unroll 8
    for (int d = 0; d < 64; d++) {
        float a0 = qs[r0 + 0][d], a1 = qs[r0 + 1][d], a2 = qs[r0 + 2][d], a3 = qs[r0 + 3][d];
        float b0 = kvs[d][e0 + 0], b1 = kvs[d][e0 + 1], b2 = kvs[d][e0 + 2], b3 = kvs[d][e0 + 3];
        acc[0][0] += a0 * b0; acc[0][1] += a0 * b1; acc[0][2] += a0 * b2; acc[0][3] += a0 * b3;
        acc[1][0] += a1 * b0; acc[1][1] += a1 * b1; acc[1][2] += a1 * b2; acc[1][3] += a1 * b3;
        acc[2][0] += a2 * b0; acc[2][1] += a2 * b1; acc[2][2] += a2 * b2; acc[2][3] += a2 * b3;
        acc[3][0] += a3 * b0; acc[3][1] += a3 * b1; acc[3][2] += a3 * b2; acc[3][3] += a3 * b3;
    }

    #pragma unroll
    for (int i = 0; i < 4; i++) {
        const int m = b * NSEQ + ch * 64 + r0 + i;
        #pragma unroll
        for (int j = 0; j < 4; j++)
            g_kb[m * CDIM + h * HDIM + e0 + j] = acc[i][j];
    }
}

// ============================================================
extern "C" void kernel_launch(void* const* d_in, const int* in_sizes, int n_in,
                              void* d_out, int out_size) {
    const float* x      = (const float*)d_in[0];   // [4,8192,512]
    const float* w_qkv  = (const float*)d_in[1];   // [1536,512]
    const float* w_proj = (const float*)d_in[2];   // [512,512]
    const float* b_proj = (const float*)d_in[3];   // [512]
    float* out = (float*)d_out;                    // [4,8192,512]

    // 1) qkv GEMM + phi + scatter
    {
        dim3 grid(QKVN / BN, MROWS / BM);   // (12, 256)
        gemm_qkv_kernel<<<grid, 256>>>(x, w_qkv);
    }
    // 2) kv state partials + reduce
    {
        dim3 grid(KV_CHUNKS, BATCH * HEADS);   // (32, 32)
        kv_partial_kernel<<<grid, 256>>>();
        kv_reduce_kernel<<<(BATCH * HEADS * HDIM * HDIM) / 256, 256>>>();
    }
    // 3) apply phi(q) @ kv  (writes g_kb)
    {
        dim3 grid(NSEQ / 64, BATCH * HEADS);   // (128, 32)
        attn_apply_kernel<<<grid, 256>>>();
    }
    // 4) proj GEMM + bias (reads g_kb)
    {
        dim3 grid(CDIM / BN, MROWS / BM);   // (4, 256)
        gemm_proj_kernel<<<grid, 256>>>(w_proj, b_proj, out);
    }
}

// round 6
// speedup vs baseline: 2.6545x; 2.6545x over previous
#include <cuda_runtime.h>
#include <cuda_bf16.h>
#include <math.h>
#include <cstdint>

// Problem constants
#define BATCH   4
#define NSEQ    8192
#define CDIM    512
#define HEADS   8
#define HDIM    64
#define MROWS   (BATCH * NSEQ)      // 32768
#define QKVN    (3 * CDIM)          // 1536
#define SCALE   0.125f

// ---- scratch (device globals; no allocation allowed) ----
__device__ float g_qb[MROWS * CDIM];     // phi(q)
__device__ float g_kb[MROWS * CDIM];     // phi(k), later: attention output
__device__ float g_vb[MROWS * CDIM];     // v
#define KV_CHUNKS 32
__device__ float g_partial[KV_CHUNKS * BATCH * HEADS * HDIM * HDIM];
__device__ float g_kv[BATCH * HEADS * HDIM * HDIM];

__device__ __forceinline__ float phi_f(float x) {
    return (x > 0.0f) ? (x + 1.0f) : expf(x);
}

__device__ __forceinline__ uint32_t smem_u32(const void* p) {
    uint32_t a;
    asm("{ .reg .u64 t; cvta.to.shared.u64 t, %1; cvt.u32.u64 %0, t; }" : "=r"(a) : "l"(p));
    return a;
}

__device__ __forceinline__ uint32_t bf16pair(float hi, float lo) {
    uint32_t r;
    asm("cvt.rn.bf16x2.f32 %0, %1, %2;" : "=r"(r) : "f"(hi), "f"(lo));
    return r;
}

// ldmatrix x4 (b16)
#define LDSM_X4(r0, r1, r2, r3, addr) \
    asm volatile("ldmatrix.sync.aligned.m8n8.x4.shared.b16 {%0,%1,%2,%3}, [%4];" \
                 : "=r"(r0), "=r"(r1), "=r"(r2), "=r"(r3) : "r"(addr))

// mma m16n8k16 bf16 -> f32 accumulate
#define MMA16816(c, a, b) \
    asm volatile("mma.sync.aligned.m16n8k16.row.col.f32.bf16.bf16.f32 " \
                 "{%0,%1,%2,%3}, {%4,%5,%6,%7}, {%8,%9}, {%0,%1,%2,%3};" \
                 : "+f"((c)[0]), "+f"((c)[1]), "+f"((c)[2]), "+f"((c)[3]) \
                 : "r"((a)[0]), "r"((a)[1]), "r"((a)[2]), "r"((a)[3]), \
                   "r"((b)[0]), "r"((b)[1]))

// ============================================================
// HMMA GEMM: C[m,n] = sum_k A[m,k] * W[n,k]
// CTA 128x128, K chunks of 16 (bf16 big+small split, 3 passes).
// smem rows padded to 24 bf16 (48 B) -> conflict-free ldmatrix.
// Double-buffered stage fits in 48 KB -> no cudaFuncSetAttribute needed.
// ============================================================
#define GBK       16
#define NCHUNK    (CDIM / GBK)      // 32
#define TSTRIDE   24                // bf16 per row (16 + 8 pad)
#define RB        (TSTRIDE * 2)     // 48 bytes per row
#define TBYTES    (128 * RB)        // 6144 per matrix
#define STAGE_B   (4 * TBYTES)      // Abig|Asmall|Bbig|Bsmall = 24576
#define GSMEM     (2 * STAGE_B)     // 49152 = 48 KB (no opt-in required)

__global__ __launch_bounds__(256) void mma_gemm_kernel(
    const float* __restrict__ Ain,
    const float* __restrict__ W,
    const float* __restrict__ bias,
    float* __restrict__ Y,
    int mode)       // 0: qkv (phi+scatter), 1: proj (+bias -> Y)
{
    extern __shared__ char dsm[];
    const uint32_t sb = smem_u32(dsm);
    const int t = threadIdx.x;
    const int wid = t >> 5;
    const int lane = t & 31;

    const float* A = (mode == 1) ? g_kb : Ain;

    const int m0 = blockIdx.y * 128;
    const int n0 = blockIdx.x * 128;

    const int warpM = wid >> 2;          // 0..1
    const int warpN = wid & 3;           // 0..3

    // ldmatrix lane address offsets (bytes) within a tile
    const int lr = lane & 7;
    const int lm = lane >> 3;
    const int laneA = (lr + ((lm & 1) << 3)) * RB + ((lm >> 1) << 4);
    const int laneB = (((lm >> 1) << 3) + lr) * RB + ((lm & 1) << 4);

    float4 pa[2], pb[2];

    // per-thread fill coords: 512 float4 per 128x16 tile, 2 per thread
    // idx = t + i*256 ; row = idx>>2 ; colq = idx&3

    // ---- prologue: load + convert/split + store chunk 0 ----
    {
        #pragma unroll
        for (int i = 0; i < 2; i++) {
            int idx = t + i * 256;
            int row = idx >> 2, colq = idx & 3;
            pa[i] = *(const float4*)(A + (size_t)(m0 + row) * CDIM + colq * 4);
            pb[i] = *(const float4*)(W + (size_t)(n0 + row) * CDIM + colq * 4);
        }
        char* base = dsm;
        #pragma unroll
        for (int i = 0; i < 2; i++) {
            int idx = t + i * 256;
            int row = idx >> 2, colq = idx & 3;
            uint32_t off = row * RB + colq * 8;
            float4 v = pa[i];
            uint32_t b01 = bf16pair(v.y, v.x), b23 = bf16pair(v.w, v.z);
            float f0 = __uint_as_float(b01 << 16), f1 = __uint_as_float(b01 & 0xffff0000u);
            float f2 = __uint_as_float(b23 << 16), f3 = __uint_as_float(b23 & 0xffff0000u);
            *(uint2*)(base + off) = make_uint2(b01, b23);
            *(uint2*)(base + TBYTES + off) =
                make_uint2(bf16pair(v.y - f1, v.x - f0), bf16pair(v.w - f3, v.z - f2));
            v = pb[i];
            b01 = bf16pair(v.y, v.x); b23 = bf16pair(v.w, v.z);
            f0 = __uint_as_float(b01 << 16); f1 = __uint_as_float(b01 & 0xffff0000u);
            f2 = __uint_as_float(b23 << 16); f3 = __uint_as_float(b23 & 0xffff0000u);
            *(uint2*)(base + 2 * TBYTES + off) = make_uint2(b01, b23);
            *(uint2*)(base + 3 * TBYTES + off) =
                make_uint2(bf16pair(v.y - f1, v.x - f0), bf16pair(v.w - f3, v.z - f2));
        }
    }
    __syncthreads();

    float acc[4][4][4];
    #pragma unroll
    for (int i = 0; i < 4; i++)
        #pragma unroll
        for (int j = 0; j < 4; j++)
            #pragma unroll
            for (int e = 0; e < 4; e++) acc[i][j][e] = 0.0f;

    for (int c = 0; c < NCHUNK; c++) {
        // prefetch next chunk into regs
        if (c + 1 < NCHUNK) {
            const int k0 = (c + 1) * GBK;
            #pragma unroll
            for (int i = 0; i < 2; i++) {
                int idx = t + i * 256;
                int row = idx >> 2, colq = idx & 3;
                pa[i] = *(const float4*)(A + (size_t)(m0 + row) * CDIM + k0 + colq * 4);
                pb[i] = *(const float4*)(W + (size_t)(n0 + row) * CDIM + k0 + colq * 4);
            }
        }

        // compute chunk c from smem buffer c&1
        const uint32_t buf = sb + (uint32_t)(c & 1) * STAGE_B;
        const uint32_t sAb = buf;
        const uint32_t sAs = buf + TBYTES;
        const uint32_t sBb = buf + 2 * TBYTES;
        const uint32_t sBs = buf + 3 * TBYTES;

        {
            uint32_t Bb[4][2], Bs[4][2];
            #pragma unroll
            for (int p = 0; p < 2; p++) {
                uint32_t addr = sBb + (warpN * 32 + p * 16) * RB + laneB;
                LDSM_X4(Bb[2 * p][0], Bb[2 * p][1], Bb[2 * p + 1][0], Bb[2 * p + 1][1], addr);
                addr = sBs + (warpN * 32 + p * 16) * RB + laneB;
                LDSM_X4(Bs[2 * p][0], Bs[2 * p][1], Bs[2 * p + 1][0], Bs[2 * p + 1][1], addr);
            }
            #pragma unroll
            for (int mi = 0; mi < 4; mi++) {
                uint32_t ab[4], as_[4];
                uint32_t addr = sAb + (warpM * 64 + mi * 16) * RB + laneA;
                LDSM_X4(ab[0], ab[1], ab[2], ab[3], addr);
                addr = sAs + (warpM * 64 + mi * 16) * RB + laneA;
                LDSM_X4(as_[0], as_[1], as_[2], as_[3], addr);
                #pragma unroll
                for (int nf = 0; nf < 4; nf++) MMA16816(acc[mi][nf], ab, Bb[nf]);
                #pragma unroll
                for (int nf = 0; nf < 4; nf++) MMA16816(acc[mi][nf], ab, Bs[nf]);
                #pragma unroll
                for (int nf = 0; nf < 4; nf++) MMA16816(acc[mi][nf], as_, Bb[nf]);
            }
        }

        // store prefetched chunk into the other buffer
        if (c + 1 < NCHUNK) {
            char* base = dsm + ((c + 1) & 1) * STAGE_B;
            #pragma unroll
            for (int i = 0; i < 2; i++) {
                int idx = t + i * 256;
                int row = idx >> 2, colq = idx & 3;
                uint32_t off = row * RB + colq * 8;
                float4 v = pa[i];
                uint32_t b01 = bf16pair(v.y, v.x), b23 = bf16pair(v.w, v.z);
                float f0 = __uint_as_float(b01 << 16), f1 = __uint_as_float(b01 & 0xffff0000u);
                float f2 = __uint_as_float(b23 << 16), f3 = __uint_as_float(b23 & 0xffff0000u);
                *(uint2*)(base + off) = make_uint2(b01, b23);
                *(uint2*)(base + TBYTES + off) =
                    make_uint2(bf16pair(v.y - f1, v.x - f0), bf16pair(v.w - f3, v.z - f2));
                v = pb[i];
                b01 = bf16pair(v.y, v.x); b23 = bf16pair(v.w, v.z);
                f0 = __uint_as_float(b01 << 16); f1 = __uint_as_float(b01 & 0xffff0000u);
                f2 = __uint_as_float(b23 << 16); f3 = __uint_as_float(b23 & 0xffff0000u);
                *(uint2*)(base + 2 * TBYTES + off) = make_uint2(b01, b23);
                *(uint2*)(base + 3 * TBYTES + off) =
                    make_uint2(bf16pair(v.y - f1, v.x - f0), bf16pair(v.w - f3, v.z - f2));
            }
        }
        __syncthreads();
    }

    // ---- epilogue: direct stores from C frags ----
    const int g  = lane >> 2;
    const int q4 = lane & 3;

    if (mode == 0) {
        const int sblk = n0 >> 9;   // 0=q 1=k 2=v
        float* outp = (sblk == 0) ? g_qb : (sblk == 1) ? g_kb : g_vb;
        const int c0 = n0 & 511;
        #pragma unroll
        for (int mi = 0; mi < 4; mi++) {
            #pragma unroll
            for (int nf = 0; nf < 4; nf++) {
                const int row = m0 + warpM * 64 + mi * 16 + g;
                const int col = c0 + warpN * 32 + nf * 8 + q4 * 2;
                float v0 = acc[mi][nf][0], v1 = acc[mi][nf][1];
                float v2 = acc[mi][nf][2], v3 = acc[mi][nf][3];
                if (sblk < 2) { v0 = phi_f(v0); v1 = phi_f(v1); v2 = phi_f(v2); v3 = phi_f(v3); }
                *(float2*)(outp + (size_t)row * CDIM + col)       = make_float2(v0, v1);
                *(float2*)(outp + (size_t)(row + 8) * CDIM + col) = make_float2(v2, v3);
            }
        }
    } else {
        #pragma unroll
        for (int mi = 0; mi < 4; mi++) {
            #pragma unroll
            for (int nf = 0; nf < 4; nf++) {
                const int row = m0 + warpM * 64 + mi * 16 + g;
                const int col = n0 + warpN * 32 + nf * 8 + q4 * 2;
                const float bz0 = bias[col], bz1 = bias[col + 1];
                *(float2*)(Y + (size_t)row * CDIM + col) =
                    make_float2(acc[mi][nf][0] + bz0, acc[mi][nf][1] + bz1);
                *(float2*)(Y + (size_t)(row + 8) * CDIM + col) =
                    make_float2(acc[mi][nf][2] + bz0, acc[mi][nf][3] + bz1);
            }
        }
    }
}

// ============================================================
// kv partials / reduce / apply (unchanged fp32)
// ============================================================
__global__ __launch_bounds__(256) void kv_partial_kernel()
{
    const int ch = blockIdx.x;
    const int bh = blockIdx.y;
    const int b = bh >> 3, h = bh & 7;
    const int rows = NSEQ / KV_CHUNKS;
    const int base_m = b * NSEQ + ch * rows;

    const int t = threadIdx.x;
    const int d0 = (t >> 4) * 4;
    const int e0 = (t & 15) * 4;

    __shared__ float ks[4][64];
    __shared__ float vs[4][64];

    float acc[4][4];
    #pragma unroll
    for (int i = 0; i < 4; i++)
        #pragma unroll
        for (int j = 0; j < 4; j++) acc[i][j] = 0.0f;

    const int lr = t >> 6;
    const int lc = t & 63;

    for (int n = 0; n < rows; n += 4) {
        const int m = base_m + n + lr;
        ks[lr][lc] = g_kb[m * CDIM + h * HDIM + lc];
        vs[lr][lc] = g_vb[m * CDIM + h * HDIM + lc];
        __syncthreads();
        #pragma unroll
        for (int r = 0; r < 4; r++) {
            float a0 = ks[r][d0 + 0], a1 = ks[r][d0 + 1], a2 = ks[r][d0 + 2], a3 = ks[r][d0 + 3];
            float b0 = vs[r][e0 + 0], b1 = vs[r][e0 + 1], b2 = vs[r][e0 + 2], b3 = vs[r][e0 + 3];
            acc[0][0] += a0 * b0; acc[0][1] += a0 * b1; acc[0][2] += a0 * b2; acc[0][3] += a0 * b3;
            acc[1][0] += a1 * b0; acc[1][1] += a1 * b1; acc[1][2] += a1 * b2; acc[1][3] += a1 * b3;
            acc[2][0] += a2 * b0; acc[2][1] += a2 * b1; acc[2][2] += a2 * b2; acc[2][3] += a2 * b3;
            acc[3][0] += a3 * b0; acc[3][1] += a3 * b1; acc[3][2] += a3 * b2; acc[3][3] += a3 * b3;
        }
        __syncthreads();
    }

    float* p = g_partial + (ch * (BATCH * HEADS) + bh) * (HDIM * HDIM);
    #pragma unroll
    for (int i = 0; i < 4; i++)
        #pragma unroll
        for (int j = 0; j < 4; j++)
            p[(d0 + i) * HDIM + (e0 + j)] = acc[i][j];
}

__global__ __launch_bounds__(256) void kv_reduce_kernel()
{
    const int idx = blockIdx.x * 256 + threadIdx.x;
    const int bh = idx >> 12;
    const int de = idx & 4095;
    float s = 0.0f;
    #pragma unroll
    for (int ch = 0; ch < KV_CHUNKS; ch++)
        s += g_partial[(ch * (BATCH * HEADS) + bh) * (HDIM * HDIM) + de];
    g_kv[idx] = s * SCALE;
}

__global__ __launch_bounds__(256) void attn_apply_kernel()
{
    const int ch = blockIdx.x;
    const int bh = blockIdx.y;
    const int b = bh >> 3, h = bh & 7;

    __shared__ float kvs[64][65];
    __shared__ float qs[64][65];

    const int t = threadIdx.x;

    #pragma unroll
    for (int i = 0; i < 16; i++) {
        const int idx = i * 256 + t;
        const int r = idx >> 6, d = idx & 63;
        kvs[r][d] = g_kv[bh * (HDIM * HDIM) + idx];
        qs[r][d]  = g_qb[(b * NSEQ + ch * 64 + r) * CDIM + h * HDIM + d];
    }
    __syncthreads();

    const int r0 = (t >> 4) * 4;
    const int e0 = (t & 15) * 4;

    float acc[4][4];
    #pragma unroll
    for (int i = 0; i < 4; i++)
        #pragma unroll
        for (int j = 0; j < 4; j++) acc[i][j] = 0.0f;

    #pragma unroll 8
    for (int d = 0; d < 64; d++) {
        float a0 = qs[r0 + 0][d], a1 = qs[r0 + 1][d], a2 = qs[r0 + 2][d], a3 = qs[r0 + 3][d];
        float b0 = kvs[d][e0 + 0], b1 = kvs[d][e0 + 1], b2 = kvs[d][e0 + 2], b3 = kvs[d][e0 + 3];
        acc[0][0] += a0 * b0; acc[0][1] += a0 * b1; acc[0][2] += a0 * b2; acc[0][3] += a0 * b3;
        acc[1][0] += a1 * b0; acc[1][1] += a1 * b1; acc[1][2] += a1 * b2; acc[1][3] += a1 * b3;
        acc[2][0] += a2 * b0; acc[2][1] += a2 * b1; acc[2][2] += a2 * b2; acc[2][3] += a2 * b3;
        acc[3][0] += a3 * b0; acc[3][1] += a3 * b1; acc[3][2] += a3 * b2; acc[3][3] += a3 * b3;
    }

    #pragma unroll
    for (int i = 0; i < 4; i++) {
        const int m = b * NSEQ + ch * 64 + r0 + i;
        #pragma unroll
        for (int j = 0; j < 4; j++)
            g_kb[m * CDIM + h * HDIM + e0 + j] = acc[i][j];
    }
}

// ============================================================
extern "C" void kernel_launch(void* const* d_in, const int* in_sizes, int n_in,
                              void* d_out, int out_size) {
    const float* x      = (const float*)d_in[0];   // [4,8192,512]
    const float* w_qkv  = (const float*)d_in[1];   // [1536,512]
    const float* w_proj = (const float*)d_in[2];   // [512,512]
    const float* b_proj = (const float*)d_in[3];   // [512]
    float* out = (float*)d_out;                    // [4,8192,512]

    // 1) qkv GEMM (HMMA) + phi + scatter
    {
        dim3 grid(QKVN / 128, MROWS / 128);   // (12, 256)
        mma_gemm_kernel<<<grid, 256, GSMEM>>>(x, w_qkv, nullptr, nullptr, 0);
    }
    // 2) kv state partials + reduce
    {
        dim3 grid(KV_CHUNKS, BATCH * HEADS);
        kv_partial_kernel<<<grid, 256>>>();
        kv_reduce_kernel<<<(BATCH * HEADS * HDIM * HDIM) / 256, 256>>>();
    }
    // 3) apply phi(q) @ kv  (writes g_kb)
    {
        dim3 grid(NSEQ / 64, BATCH * HEADS);
        attn_apply_kernel<<<grid, 256>>>();
    }
    // 4) proj GEMM (HMMA) + bias (reads g_kb)
    {
        dim3 grid(CDIM / 128, MROWS / 128);   // (4, 256)
        mma_gemm_kernel<<<grid, 256, GSMEM>>>(nullptr, w_proj, b_proj, out, 1);
    }
}